// round 5
// baseline (speedup 1.0000x reference)
#include <cuda_runtime.h>
#include <cuda_bf16.h>
#include <cstdint>

// Problem constants (fixed by the dataset): D=64, H=256, G=4096.
#define DREP 64
#define HID 256
#define MAXG 4096
#define BN_EPS 1e-3f

// Scratch: per-graph pooled sums [G, D]. Static device array (no allocation).
__device__ float g_pooled[MAXG * DREP];

// ---------------------------------------------------------------------------
// helpers
// ---------------------------------------------------------------------------
__device__ __forceinline__ unsigned pack_bf16x2(float lo, float hi) {
    unsigned r;
    asm("cvt.rn.bf16x2.f32 %0, %1, %2;" : "=r"(r) : "f"(hi), "f"(lo));
    return r;
}

__device__ __forceinline__ void mma_bf16(float* c, const unsigned* a, unsigned b0, unsigned b1) {
    asm volatile(
        "mma.sync.aligned.m16n8k16.row.col.f32.bf16.bf16.f32 "
        "{%0,%1,%2,%3},{%4,%5,%6,%7},{%8,%9},{%0,%1,%2,%3};"
        : "+f"(c[0]), "+f"(c[1]), "+f"(c[2]), "+f"(c[3])
        : "r"(a[0]), "r"(a[1]), "r"(a[2]), "r"(a[3]), "r"(b0), "r"(b1));
}

__device__ __forceinline__ float tanh_fast(float u) {
    float r;
    asm("tanh.approx.f32 %0, %1;" : "=f"(r) : "f"(u));
    return r;
}

// RR = sigmoid(tanh(u)) * relu(j);  sigmoid(t) = 0.5 + 0.5*tanh(0.5*t)
__device__ __forceinline__ float gated_act(float u, float j) {
    float t  = tanh_fast(u);
    float s  = fmaf(0.5f, tanh_fast(0.5f * t), 0.5f);
    return s * fmaxf(j, 0.0f);
}

// ---------------------------------------------------------------------------
// kernel 0: zero the pooled accumulator
// ---------------------------------------------------------------------------
__global__ void __launch_bounds__(256) zero_pooled_kernel(int n) {
    for (int i = blockIdx.x * blockDim.x + threadIdx.x; i < n; i += gridDim.x * blockDim.x)
        g_pooled[i] = 0.0f;
}

// ---------------------------------------------------------------------------
// kernel 1: per-node gated dense (bf16 mma) + sorted segment-sum
//   tile = 128 nodes; 8 warps in a 4m x 2n grid: each warp owns 32 rows x 32
//   output dims. ALL weight (B) fragments live in registers, loaded once per
//   block -> zero ldmatrix / zero smem weight traffic in the main loop.
//   A fragments loaded straight from gmem (float2 per lane -> bf16x2);
//   the n-pair warp's duplicate A reads hit L1.
//   sRR / sSeg double-buffered -> one __syncthreads per tile.
// ---------------------------------------------------------------------------
__global__ void __launch_bounds__(256, 1) node_kernel(
    const float* __restrict__ x, const float* __restrict__ h,
    const float* __restrict__ Wi, const float* __restrict__ bi,
    const float* __restrict__ Wj, const float* __restrict__ bj,
    const int* __restrict__ seg, int N, int T, int TPB)
{
    __shared__ __nv_bfloat16 sRR[2][128 * 72];
    __shared__ int           sSeg[2][128];

    const int tid  = threadIdx.x;
    const int warp = tid >> 5, lane = tid & 31;
    const int wm = warp & 3;        // m-quadrant: rows wm*32 .. +32
    const int wn = warp >> 2;       // n-half:     cols wn*32 .. +32
    const int g = lane >> 2, t = lane & 3;

    // ------------------ hoist B fragments into registers -------------------
    // mma.sync m16n8k16 B layout (col-major B = our [k][n] row-major W):
    //   lane: n = nt*8 + g ; reg0 = {W[k0][n], W[k0+1][n]}, k0 = ks*16 + 2t
    //         reg1 = {W[k0+8][n], W[k0+9][n]}
    unsigned B1[8][4][2];   // Wi: k = 128 (h then x), n-range = wn*32..+32
    unsigned B2[4][4][2];   // Wj: k = 64
    #pragma unroll
    for (int ks = 0; ks < 8; ks++)
        #pragma unroll
        for (int nt = 0; nt < 4; nt++) {
            int n  = wn * 32 + nt * 8 + g;
            int k0 = ks * 16 + 2 * t;
            B1[ks][nt][0] = pack_bf16x2(Wi[k0 * 64 + n],       Wi[(k0 + 1) * 64 + n]);
            B1[ks][nt][1] = pack_bf16x2(Wi[(k0 + 8) * 64 + n], Wi[(k0 + 9) * 64 + n]);
        }
    #pragma unroll
    for (int ks = 0; ks < 4; ks++)
        #pragma unroll
        for (int nt = 0; nt < 4; nt++) {
            int n  = wn * 32 + nt * 8 + g;
            int k0 = ks * 16 + 2 * t;
            B2[ks][nt][0] = pack_bf16x2(Wj[k0 * 64 + n],       Wj[(k0 + 1) * 64 + n]);
            B2[ks][nt][1] = pack_bf16x2(Wj[(k0 + 8) * 64 + n], Wj[(k0 + 9) * 64 + n]);
        }

    // hoist biases (per-lane output columns are fixed)
    float biv[4][2], bjv[4][2];
    #pragma unroll
    for (int nt = 0; nt < 4; nt++) {
        int c0 = wn * 32 + nt * 8 + 2 * t;
        biv[nt][0] = bi[c0]; biv[nt][1] = bi[c0 + 1];
        bjv[nt][0] = bj[c0]; bjv[nt][1] = bj[c0 + 1];
    }

    const int t0 = blockIdx.x * TPB;
    const int t1 = min(T, t0 + TPB);
    const int segDim   = tid & 63;
    const int segChunk = tid >> 6;
    const float2 zz = make_float2(0.f, 0.f);

    int p = 0;
    for (int tile = t0; tile < t1; ++tile) {
        const int rowBase = tile * 128;

        if (tid < 128) {
            int r = rowBase + tid;
            sSeg[p][tid] = (r < N) ? seg[r] : -1;
        }

        float ai[2][4][4], aj[2][4][4];
        #pragma unroll
        for (int mt = 0; mt < 2; mt++)
            #pragma unroll
            for (int nt = 0; nt < 4; nt++)
                #pragma unroll
                for (int q = 0; q < 4; q++) { ai[mt][nt][q] = 0.f; aj[mt][nt][q] = 0.f; }

        #pragma unroll
        for (int mt = 0; mt < 2; mt++) {
            const int r0 = rowBase + wm * 32 + mt * 16 + g;
            const int r1 = r0 + 8;
            const bool ok0 = r0 < N, ok1 = r1 < N;
            const float* h0 = h + (size_t)r0 * 64;
            const float* h1 = h + (size_t)r1 * 64;
            const float* x0 = x + (size_t)r0 * 64;
            const float* x1 = x + (size_t)r1 * 64;

            // ---- h phase: GEMM1 k[0,64) + GEMM2 (full) ----
            unsigned A[4][4];
            #pragma unroll
            for (int ks = 0; ks < 4; ks++) {
                int c0 = ks * 16 + 2 * t, c1 = c0 + 8;
                float2 f0 = ok0 ? *(const float2*)(h0 + c0) : zz;
                float2 f1 = ok1 ? *(const float2*)(h1 + c0) : zz;
                float2 f2 = ok0 ? *(const float2*)(h0 + c1) : zz;
                float2 f3 = ok1 ? *(const float2*)(h1 + c1) : zz;
                A[ks][0] = pack_bf16x2(f0.x, f0.y);
                A[ks][1] = pack_bf16x2(f1.x, f1.y);
                A[ks][2] = pack_bf16x2(f2.x, f2.y);
                A[ks][3] = pack_bf16x2(f3.x, f3.y);
            }
            #pragma unroll
            for (int ks = 0; ks < 4; ks++)
                #pragma unroll
                for (int nt = 0; nt < 4; nt++) {
                    mma_bf16(ai[mt][nt], A[ks], B1[ks][nt][0], B1[ks][nt][1]);
                    mma_bf16(aj[mt][nt], A[ks], B2[ks][nt][0], B2[ks][nt][1]);
                }

            // ---- x phase: GEMM1 k[64,128) ----
            #pragma unroll
            for (int ks = 0; ks < 4; ks++) {
                int c0 = ks * 16 + 2 * t, c1 = c0 + 8;
                float2 f0 = ok0 ? *(const float2*)(x0 + c0) : zz;
                float2 f1 = ok1 ? *(const float2*)(x1 + c0) : zz;
                float2 f2 = ok0 ? *(const float2*)(x0 + c1) : zz;
                float2 f3 = ok1 ? *(const float2*)(x1 + c1) : zz;
                A[ks][0] = pack_bf16x2(f0.x, f0.y);
                A[ks][1] = pack_bf16x2(f1.x, f1.y);
                A[ks][2] = pack_bf16x2(f2.x, f2.y);
                A[ks][3] = pack_bf16x2(f3.x, f3.y);
            }
            #pragma unroll
            for (int ks = 0; ks < 4; ks++)
                #pragma unroll
                for (int nt = 0; nt < 4; nt++)
                    mma_bf16(ai[mt][nt], A[ks], B1[ks + 4][nt][0], B1[ks + 4][nt][1]);
        }

        // ---------------- epilogue: activations -> sRR (bf16) --------------
        #pragma unroll
        for (int mt = 0; mt < 2; mt++) {
            const int lr0 = wm * 32 + mt * 16 + g, lr1 = lr0 + 8;
            #pragma unroll
            for (int nt = 0; nt < 4; nt++) {
                int col0 = wn * 32 + nt * 8 + 2 * t;
                float rr0 = gated_act(ai[mt][nt][0] + biv[nt][0], aj[mt][nt][0] + bjv[nt][0]);
                float rr1 = gated_act(ai[mt][nt][1] + biv[nt][1], aj[mt][nt][1] + bjv[nt][1]);
                float rr2 = gated_act(ai[mt][nt][2] + biv[nt][0], aj[mt][nt][2] + bjv[nt][0]);
                float rr3 = gated_act(ai[mt][nt][3] + biv[nt][1], aj[mt][nt][3] + bjv[nt][1]);
                *(unsigned*)&sRR[p][lr0 * 72 + col0] = pack_bf16x2(rr0, rr1);
                *(unsigned*)&sRR[p][lr1 * 72 + col0] = pack_bf16x2(rr2, rr3);
            }
        }
        __syncthreads();

        // ---------------- segment accumulation (sorted run-length) ---------
        {
            const int base = segChunk * 32;
            int cur = sSeg[p][base];
            float run = 0.0f;
            #pragma unroll 4
            for (int r = 0; r < 32; r++) {
                int rr = base + r;
                float v = __bfloat162float(sRR[p][rr * 72 + segDim]);
                int s = sSeg[p][rr];
                if (s != cur) {
                    if (cur >= 0) atomicAdd(&g_pooled[cur * 64 + segDim], run);
                    cur = s; run = v;
                } else {
                    run += v;
                }
            }
            if (cur >= 0) atomicAdd(&g_pooled[cur * 64 + segDim], run);
        }
        p ^= 1;   // no trailing sync needed: next tile writes the other buffer
    }
}

// ---------------------------------------------------------------------------
// kernel 2: BN (inference) + relu(@W_h1 + b1) + @W_out + b_out
//   16 graphs per block; thread t = hidden dim t.
// ---------------------------------------------------------------------------
__global__ void __launch_bounds__(256) readout_kernel(
    const float* __restrict__ gamma, const float* __restrict__ beta,
    const float* __restrict__ mmean, const float* __restrict__ mvar,
    const float* __restrict__ W1, const float* __restrict__ b1,
    const float* __restrict__ W2, const float* __restrict__ b2,
    float* __restrict__ out, int G)
{
    __shared__ float v[16 * 64];
    __shared__ float red[8];
    const int tid = threadIdx.x;
    const int g0 = blockIdx.x * 16;

    for (int idx = tid; idx < 16 * 64; idx += 256) {
        int gg = idx >> 6, d = idx & 63;
        int gi = g0 + gg;
        float pl = (gi < G) ? g_pooled[gi * 64 + d] : 0.f;
        v[idx] = (pl - mmean[d]) * rsqrtf(mvar[d] + BN_EPS) * gamma[d] + beta[d];
    }
    __syncthreads();

    const float wout = W2[tid];
    const float bh = b1[tid];
    for (int gg = 0; gg < 16; gg++) {
        const float* vg = v + gg * 64;
        float acc = bh;
        #pragma unroll
        for (int k = 0; k < 64; k++)
            acc = fmaf(vg[k], W1[k * 256 + tid], acc);
        float c = fmaxf(acc, 0.f) * wout;
        #pragma unroll
        for (int o = 16; o > 0; o >>= 1)
            c += __shfl_down_sync(0xffffffff, c, o);
        if ((tid & 31) == 0) red[tid >> 5] = c;
        __syncthreads();
        if (tid == 0) {
            float s = b2[0];
            #pragma unroll
            for (int w = 0; w < 8; w++) s += red[w];
            if (g0 + gg < G) out[g0 + gg] = s;
        }
        __syncthreads();
    }
}

// ---------------------------------------------------------------------------
// launch
// ---------------------------------------------------------------------------
extern "C" void kernel_launch(void* const* d_in, const int* in_sizes, int n_in,
                              void* d_out, int out_size)
{
    const float* x     = (const float*)d_in[0];
    const float* h     = (const float*)d_in[1];
    const float* Wi    = (const float*)d_in[2];
    const float* bi    = (const float*)d_in[3];
    const float* Wj    = (const float*)d_in[4];
    const float* bj    = (const float*)d_in[5];
    const float* gamma = (const float*)d_in[6];
    const float* beta  = (const float*)d_in[7];
    const float* mmean = (const float*)d_in[8];
    const float* mvar  = (const float*)d_in[9];
    const float* W1    = (const float*)d_in[10];
    const float* b1    = (const float*)d_in[11];
    const float* W2    = (const float*)d_in[12];
    const float* b2    = (const float*)d_in[13];
    const int*   seg   = (const int*)d_in[14];

    const int N = in_sizes[0] / DREP;
    const int G = out_size;

    zero_pooled_kernel<<<128, 256>>>(G * DREP);

    const int T = (N + 127) / 128;
    const int BLOCKS = 148;                 // 1 resident CTA per SM, single wave
    const int TPB = (T + BLOCKS - 1) / BLOCKS;
    node_kernel<<<BLOCKS, 256>>>(x, h, Wi, bi, Wj, bj, seg, N, T, TPB);

    readout_kernel<<<(G + 15) / 16, 256>>>(gamma, beta, mmean, mvar,
                                           W1, b1, W2, b2, (float*)d_out, G);
}

// round 6
// speedup vs baseline: 2.9005x; 2.9005x over previous
#include <cuda_runtime.h>
#include <cuda_bf16.h>
#include <cstdint>

// Problem constants (fixed by the dataset): D=64, H=256, G=4096.
#define DREP 64
#define HID 256
#define MAXG 4096
#define BN_EPS 1e-3f

// Scratch: per-graph pooled sums [G, D]. Zero-initialized at module load;
// readout_kernel re-zeroes its slice after consuming it, so every
// kernel_launch invocation starts from zeros (deterministic).
__device__ float g_pooled[MAXG * DREP];

// ---------------------------------------------------------------------------
// helpers
// ---------------------------------------------------------------------------
__device__ __forceinline__ unsigned pack_bf16x2(float lo, float hi) {
    unsigned r;
    asm("cvt.rn.bf16x2.f32 %0, %1, %2;" : "=r"(r) : "f"(hi), "f"(lo));
    return r;
}

__device__ __forceinline__ void ldsm2t(unsigned& b0, unsigned& b1, unsigned addr) {
    asm volatile("ldmatrix.sync.aligned.m8n8.x2.trans.shared.b16 {%0,%1}, [%2];"
                 : "=r"(b0), "=r"(b1) : "r"(addr));
}

__device__ __forceinline__ void mma_bf16(float* c, const unsigned* a, unsigned b0, unsigned b1) {
    asm volatile(
        "mma.sync.aligned.m16n8k16.row.col.f32.bf16.bf16.f32 "
        "{%0,%1,%2,%3},{%4,%5,%6,%7},{%8,%9},{%0,%1,%2,%3};"
        : "+f"(c[0]), "+f"(c[1]), "+f"(c[2]), "+f"(c[3])
        : "r"(a[0]), "r"(a[1]), "r"(a[2]), "r"(a[3]), "r"(b0), "r"(b1));
}

__device__ __forceinline__ float tanh_fast(float u) {
    float r;
    asm("tanh.approx.f32 %0, %1;" : "=f"(r) : "f"(u));
    return r;
}

// RR = sigmoid(tanh(u)) * relu(j);  sigmoid(t) = 0.5 + 0.5*tanh(0.5*t)
__device__ __forceinline__ float gated_act(float u, float j) {
    float t  = tanh_fast(u);
    float s  = fmaf(0.5f, tanh_fast(0.5f * t), 0.5f);
    return s * fmaxf(j, 0.0f);
}

// ---------------------------------------------------------------------------
// kernel 1: per-node gated dense (bf16 mma) + sorted segment-sum
//   tile = 128 nodes; 8 warps, each owns a 16-row m-slab, n = 64.
//   Weights bf16 in smem (stride 72, conflict-free ldmatrix.trans), staged
//   once per block. A fragments loaded straight from gmem.
//   Segment sum: per-warp REGISTER accumulator. A 16-row slab is segment-
//   uniform iff its endpoint seg ids match (ids are sorted). Fast path:
//   16 local FADDs. Flush on segment change via atomicAdd (L2-aggregated).
//   Non-uniform / tail slabs: guarded per-row atomics. NO per-tile barriers.
// ---------------------------------------------------------------------------
__global__ void __launch_bounds__(256, 2) node_kernel(
    const float* __restrict__ x, const float* __restrict__ h,
    const float* __restrict__ Wi, const float* __restrict__ bi,
    const float* __restrict__ Wj, const float* __restrict__ bj,
    const int* __restrict__ seg, int N, int T, int TPB)
{
    __shared__ __nv_bfloat16 sWi[128 * 72];
    __shared__ __nv_bfloat16 sWj[64 * 72];

    const int tid = threadIdx.x;

    // stage weights (fp32 -> bf16) once per block
    for (int idx = tid; idx < 128 * 64; idx += 256) {
        int r = idx >> 6, c = idx & 63;
        sWi[r * 72 + c] = __float2bfloat16(Wi[idx]);
    }
    for (int idx = tid; idx < 64 * 64; idx += 256) {
        int r = idx >> 6, c = idx & 63;
        sWj[r * 72 + c] = __float2bfloat16(Wj[idx]);
    }
    __syncthreads();   // the ONLY barrier in this kernel

    const int warp = tid >> 5, lane = tid & 31;
    const int g = lane >> 2, t = lane & 3;
    const int lrow = lane & 15;

    const unsigned wiBase = (unsigned)__cvta_generic_to_shared(sWi);
    const unsigned wjBase = (unsigned)__cvta_generic_to_shared(sWj);

    const int t0 = blockIdx.x * TPB;
    const int t1 = min(T, t0 + TPB);
    const float2 zz = make_float2(0.f, 0.f);

    // per-warp segment accumulator (16 columns per lane)
    float acc[8][2];
    #pragma unroll
    for (int nt = 0; nt < 8; nt++) { acc[nt][0] = 0.f; acc[nt][1] = 0.f; }
    int held = -1;

    for (int tile = t0; tile < t1; ++tile) {
        const int slab = tile * 128 + warp * 16;
        if (slab >= N) continue;

        // ---------------- GEMMs ----------------
        float ai[8][4], aj[8][4];
        #pragma unroll
        for (int n = 0; n < 8; n++)
            #pragma unroll
            for (int q = 0; q < 4; q++) { ai[n][q] = 0.f; aj[n][q] = 0.f; }

        const int r0 = slab + g, r1 = slab + g + 8;
        const bool v0ok = r0 < N, v1ok = r1 < N;
        const float* hr0 = h + (size_t)r0 * 64;
        const float* hr1 = h + (size_t)r1 * 64;
        const float* xr0 = x + (size_t)r0 * 64;
        const float* xr1 = x + (size_t)r1 * 64;

        // h phase: GEMM1 k[0,64) + GEMM2 (full)
        unsigned A[4][4];
        #pragma unroll
        for (int ks = 0; ks < 4; ks++) {
            int c0 = ks * 16 + 2 * t, c1 = c0 + 8;
            float2 f0 = v0ok ? *(const float2*)(hr0 + c0) : zz;
            float2 f1 = v1ok ? *(const float2*)(hr1 + c0) : zz;
            float2 f2 = v0ok ? *(const float2*)(hr0 + c1) : zz;
            float2 f3 = v1ok ? *(const float2*)(hr1 + c1) : zz;
            A[ks][0] = pack_bf16x2(f0.x, f0.y);
            A[ks][1] = pack_bf16x2(f1.x, f1.y);
            A[ks][2] = pack_bf16x2(f2.x, f2.y);
            A[ks][3] = pack_bf16x2(f3.x, f3.y);
        }
        #pragma unroll
        for (int ks = 0; ks < 4; ks++) {
            unsigned addrI = wiBase + ((ks * 16 + lrow) * 72) * 2;
            unsigned addrJ = wjBase + ((ks * 16 + lrow) * 72) * 2;
            #pragma unroll
            for (int nt = 0; nt < 8; nt++) {
                unsigned b0, b1;
                ldsm2t(b0, b1, addrI + nt * 16);
                mma_bf16(ai[nt], A[ks], b0, b1);
                ldsm2t(b0, b1, addrJ + nt * 16);
                mma_bf16(aj[nt], A[ks], b0, b1);
            }
        }

        // x phase: GEMM1 k[64,128)
        #pragma unroll
        for (int ks = 0; ks < 4; ks++) {
            int c0 = ks * 16 + 2 * t, c1 = c0 + 8;
            float2 f0 = v0ok ? *(const float2*)(xr0 + c0) : zz;
            float2 f1 = v1ok ? *(const float2*)(xr1 + c0) : zz;
            float2 f2 = v0ok ? *(const float2*)(xr0 + c1) : zz;
            float2 f3 = v1ok ? *(const float2*)(xr1 + c1) : zz;
            A[ks][0] = pack_bf16x2(f0.x, f0.y);
            A[ks][1] = pack_bf16x2(f1.x, f1.y);
            A[ks][2] = pack_bf16x2(f2.x, f2.y);
            A[ks][3] = pack_bf16x2(f3.x, f3.y);
        }
        #pragma unroll
        for (int ks = 0; ks < 4; ks++) {
            unsigned addrI = wiBase + ((64 + ks * 16 + lrow) * 72) * 2;
            #pragma unroll
            for (int nt = 0; nt < 8; nt++) {
                unsigned b0, b1;
                ldsm2t(b0, b1, addrI + nt * 16);
                mma_bf16(ai[nt], A[ks], b0, b1);
            }
        }

        // ---------------- epilogue: activations + segment accumulate -------
        const bool fullSlab = (slab + 15) < N;
        const int sFirst = __ldg(&seg[slab]);
        const int sLast  = fullSlab ? __ldg(&seg[slab + 15]) : -1;
        const bool uniform = fullSlab && (sFirst == sLast);

        if (uniform) {
            if (held != sFirst) {
                // flush previous segment's accumulator
                if (held >= 0) {
                    #pragma unroll
                    for (int nt = 0; nt < 8; nt++) {
                        int c0 = nt * 8 + 2 * t;
                        atomicAdd(&g_pooled[held * 64 + c0],     acc[nt][0]);
                        atomicAdd(&g_pooled[held * 64 + c0 + 1], acc[nt][1]);
                    }
                    #pragma unroll
                    for (int nt = 0; nt < 8; nt++) { acc[nt][0] = 0.f; acc[nt][1] = 0.f; }
                }
                held = sFirst;
            }
            #pragma unroll
            for (int nt = 0; nt < 8; nt++) {
                int c0 = nt * 8 + 2 * t;
                float bi0 = bi[c0], bi1 = bi[c0 + 1];
                float bj0 = bj[c0], bj1 = bj[c0 + 1];
                float rr0 = gated_act(ai[nt][0] + bi0, aj[nt][0] + bj0);
                float rr1 = gated_act(ai[nt][1] + bi1, aj[nt][1] + bj1);
                float rr2 = gated_act(ai[nt][2] + bi0, aj[nt][2] + bj0);
                float rr3 = gated_act(ai[nt][3] + bi1, aj[nt][3] + bj1);
                acc[nt][0] += rr0 + rr2;
                acc[nt][1] += rr1 + rr3;
            }
        } else {
            // slow path: flush, then per-row guarded atomics
            if (held >= 0) {
                #pragma unroll
                for (int nt = 0; nt < 8; nt++) {
                    int c0 = nt * 8 + 2 * t;
                    atomicAdd(&g_pooled[held * 64 + c0],     acc[nt][0]);
                    atomicAdd(&g_pooled[held * 64 + c0 + 1], acc[nt][1]);
                }
                #pragma unroll
                for (int nt = 0; nt < 8; nt++) { acc[nt][0] = 0.f; acc[nt][1] = 0.f; }
                held = -1;
            }
            const int s0 = v0ok ? __ldg(&seg[r0]) : -1;
            const int s1 = v1ok ? __ldg(&seg[r1]) : -1;
            #pragma unroll
            for (int nt = 0; nt < 8; nt++) {
                int c0 = nt * 8 + 2 * t;
                float bi0 = bi[c0], bi1 = bi[c0 + 1];
                float bj0 = bj[c0], bj1 = bj[c0 + 1];
                if (s0 >= 0) {
                    float rr0 = gated_act(ai[nt][0] + bi0, aj[nt][0] + bj0);
                    float rr1 = gated_act(ai[nt][1] + bi1, aj[nt][1] + bj1);
                    atomicAdd(&g_pooled[s0 * 64 + c0],     rr0);
                    atomicAdd(&g_pooled[s0 * 64 + c0 + 1], rr1);
                }
                if (s1 >= 0) {
                    float rr2 = gated_act(ai[nt][2] + bi0, aj[nt][2] + bj0);
                    float rr3 = gated_act(ai[nt][3] + bi1, aj[nt][3] + bj1);
                    atomicAdd(&g_pooled[s1 * 64 + c0],     rr2);
                    atomicAdd(&g_pooled[s1 * 64 + c0 + 1], rr3);
                }
            }
        }
    }

    // final flush
    if (held >= 0) {
        #pragma unroll
        for (int nt = 0; nt < 8; nt++) {
            int c0 = nt * 8 + 2 * t;
            atomicAdd(&g_pooled[held * 64 + c0],     acc[nt][0]);
            atomicAdd(&g_pooled[held * 64 + c0 + 1], acc[nt][1]);
        }
    }
}

// ---------------------------------------------------------------------------
// kernel 2: BN (inference) + relu(@W_h1 + b1) + @W_out + b_out
//   16 graphs per block. Also RE-ZEROES its g_pooled slice after reading,
//   restoring the all-zeros invariant for the next kernel_launch call.
// ---------------------------------------------------------------------------
__global__ void __launch_bounds__(256) readout_kernel(
    const float* __restrict__ gamma, const float* __restrict__ beta,
    const float* __restrict__ mmean, const float* __restrict__ mvar,
    const float* __restrict__ W1, const float* __restrict__ b1,
    const float* __restrict__ W2, const float* __restrict__ b2,
    float* __restrict__ out, int G)
{
    __shared__ float v[16 * 64];
    __shared__ float red[8];
    const int tid = threadIdx.x;
    const int g0 = blockIdx.x * 16;

    for (int idx = tid; idx < 16 * 64; idx += 256) {
        int gg = idx >> 6, d = idx & 63;
        int gi = g0 + gg;
        float p = 0.f;
        if (gi < G) {
            p = g_pooled[gi * 64 + d];
            g_pooled[gi * 64 + d] = 0.f;   // restore zero invariant
        }
        v[idx] = (p - mmean[d]) * rsqrtf(mvar[d] + BN_EPS) * gamma[d] + beta[d];
    }
    __syncthreads();

    const float wout = W2[tid];
    const float bh = b1[tid];
    for (int gg = 0; gg < 16; gg++) {
        const float* vg = v + gg * 64;
        float acc = bh;
        #pragma unroll
        for (int k = 0; k < 64; k++)
            acc = fmaf(vg[k], W1[k * 256 + tid], acc);
        float c = fmaxf(acc, 0.f) * wout;
        #pragma unroll
        for (int o = 16; o > 0; o >>= 1)
            c += __shfl_down_sync(0xffffffff, c, o);
        if ((tid & 31) == 0) red[tid >> 5] = c;
        __syncthreads();
        if (tid == 0) {
            float s = b2[0];
            #pragma unroll
            for (int w = 0; w < 8; w++) s += red[w];
            if (g0 + gg < G) out[g0 + gg] = s;
        }
        __syncthreads();
    }
}

// no-op padding kernels: bring launches-per-call to 5 so ncu (-s 5 -c 1)
// captures node_kernel (launch #5 = first replay's node). Remove once tuned.
__global__ void noop_kernel() {}

// ---------------------------------------------------------------------------
// launch
// ---------------------------------------------------------------------------
extern "C" void kernel_launch(void* const* d_in, const int* in_sizes, int n_in,
                              void* d_out, int out_size)
{
    const float* x     = (const float*)d_in[0];
    const float* h     = (const float*)d_in[1];
    const float* Wi    = (const float*)d_in[2];
    const float* bi    = (const float*)d_in[3];
    const float* Wj    = (const float*)d_in[4];
    const float* bj    = (const float*)d_in[5];
    const float* gamma = (const float*)d_in[6];
    const float* beta  = (const float*)d_in[7];
    const float* mmean = (const float*)d_in[8];
    const float* mvar  = (const float*)d_in[9];
    const float* W1    = (const float*)d_in[10];
    const float* b1    = (const float*)d_in[11];
    const float* W2    = (const float*)d_in[12];
    const float* b2    = (const float*)d_in[13];
    const int*   seg   = (const int*)d_in[14];

    const int N = in_sizes[0] / DREP;
    const int G = out_size;

    const int T = (N + 127) / 128;
    const int BLOCKS = 304;                 // 2 resident CTAs per SM
    const int TPB = (T + BLOCKS - 1) / BLOCKS;
    node_kernel<<<BLOCKS, 256>>>(x, h, Wi, bi, Wj, bj, seg, N, T, TPB);

    readout_kernel<<<(G + 15) / 16, 256>>>(gamma, beta, mmean, mvar,
                                           W1, b1, W2, b2, (float*)d_out, G);

    noop_kernel<<<1, 1>>>();
    noop_kernel<<<1, 1>>>();
    noop_kernel<<<1, 1>>>();
}